// round 14
// baseline (speedup 1.0000x reference)
#include <cuda_runtime.h>
#include <cstdint>
#include <cstdio>

#define NTOK  131072
#define DIM   128
#define NCODE 1024
#define NLVL  4

#define BM    64                 // tokens per CTA (16 per warp)
#define ARGMIN_GRID (NTOK / BM)  // 2048
#define RES_GRID    (NTOK * (DIM / 4) / 256)     // 16384
#define FINAL_ROWS  16
#define FINAL_GRID  (NTOK / FINAL_ROWS)          // 8192
#define PREP_GRID   (NLVL * NCODE / 8)           // 512

#define MARGIN 2e-4f             // capture margin in s-domain

#define BROW 132                 // padded B-row stride (words): bank-perm LDS
#define NITER (NCODE / 32)       // 32 code-tiles of 32

// ---- small float-only device global (validated safe in R12) ----
__device__ float g_en2[NLVL * NCODE];   // 16 KB

// ---- legacy tensor-core mma (sm_80+; compiles on sm_100 base) ----
#define MMA_TF32(d, a, b0, b1)                                              \
    asm volatile("mma.sync.aligned.m16n8k8.row.col.f32.tf32.tf32.f32 "      \
        "{%0,%1,%2,%3}, {%4,%5,%6,%7}, {%8,%9}, {%0,%1,%2,%3};"             \
        : "+f"((d)[0]), "+f"((d)[1]), "+f"((d)[2]), "+f"((d)[3])            \
        : "r"((a)[0]), "r"((a)[1]), "r"((a)[2]), "r"((a)[3]),               \
          "r"(b0), "r"(b1))

__device__ __forceinline__ uint32_t tf32_of(float x)
{
    uint32_t h;
    asm("cvt.rna.tf32.f32 %0, %1;" : "=r"(h) : "f"(x));
    return h;
}

__device__ __forceinline__ unsigned long long umin64(unsigned long long a,
                                                     unsigned long long b)
{ return a < b ? a : b; }
__device__ __forceinline__ unsigned long long umax64(unsigned long long a,
                                                     unsigned long long b)
{ return a > b ? a : b; }

// ---------------------------------------------------------------------------
// prep: en2[r] = sum_d e[r][d]^2 for ALL levels (bit-identical R7 formula).
// ---------------------------------------------------------------------------
__global__ void __launch_bounds__(256)
prep_kernel(const float* __restrict__ embedding, int early)
{
    if (early) return;
    int lane = threadIdx.x & 31;
    int row  = blockIdx.x * 8 + (threadIdx.x >> 5);   // 0..4095
    float4 v = reinterpret_cast<const float4*>(embedding + (size_t)row * DIM)[lane];
    float p = __fadd_rn(__fadd_rn(__fadd_rn(__fmul_rn(v.x, v.x),
                                            __fmul_rn(v.y, v.y)),
                                  __fmul_rn(v.z, v.z)),
                        __fmul_rn(v.w, v.w));
    #pragma unroll
    for (int off = 16; off >= 1; off >>= 1)
        p = __fadd_rn(p, __shfl_down_sync(0xffffffffu, p, off));
    if (lane == 0) g_en2[row] = p;
}

// exact R7-bit-identical rescore: sequential-d fp32 fmaf dot + binned dist;
// lowest-index tie-break via packed u64 atomicMin (exact dist domain).
__device__ __forceinline__ void rescore(const float4* __restrict__ srow4,
                                        const float* __restrict__ embed,
                                        const float* __restrict__ en2g,
                                        const float* rn2s,
                                        unsigned long long* cand,
                                        int row, int k)
{
    const float4* e4 = reinterpret_cast<const float4*>(embed + (size_t)k * DIM);
    float dot = 0.f;
    #pragma unroll 8
    for (int i = 0; i < 32; i++) {
        float4 a = __ldg(srow4 + i);
        float4 e = __ldg(e4 + i);
        dot = fmaf(a.x, e.x, dot);
        dot = fmaf(a.y, e.y, dot);
        dot = fmaf(a.z, e.z, dot);
        dot = fmaf(a.w, e.w, dot);
    }
    float dist = __fsub_rn(__fadd_rn(rn2s[row], __ldg(en2g + k)),
                           __fmul_rn(2.0f, dot));
    unsigned long long p =
        ((unsigned long long)__float_as_uint(dist) << 32) | (unsigned)k;
    atomicMin(cand + row, p);
}

// ---------------------------------------------------------------------------
// argmin: warps own M (16 rows each), all warps share a smem-staged 32-code
// B tile (double-buffered, coalesced). A fragments live in registers.
// Bias folded into GEMM (extra K-group). Exact rescoring of top-2 in margin.
// ---------------------------------------------------------------------------
__global__ void __launch_bounds__(128)
argmin_kernel(const float* __restrict__ src,     // N x D (inputs or residual)
              const float* __restrict__ embed,   // K x D, this level (fp32)
              const float* __restrict__ en2g,    // K, this level (from g_en2)
              float* __restrict__ idx_out,       // N floats, this level slice
              int early)
{
    if (early) return;

    __shared__ uint32_t Bs[2][32 * BROW];        // 33.8 KB double-buffered
    __shared__ float rn2s[BM];
    __shared__ unsigned long long cand[BM];

    const int tid  = threadIdx.x;
    const int wid  = tid >> 5, lane = tid & 31;
    const int r_lane = lane >> 2;   // 0..7
    const int c_lane = lane & 3;    // 0..3
    const int m0blk = blockIdx.x * BM;
    const float4* __restrict__ src4 =
        reinterpret_cast<const float4*>(src) + (size_t)m0blk * (DIM / 4);
    const float4* __restrict__ emb4 = reinterpret_cast<const float4*>(embed);

    // ---- rn2 (bit-identical R7 formula) ----
    for (int r = wid; r < BM; r += 4) {
        float4 v = src4[(size_t)r * (DIM / 4) + lane];
        float p = __fadd_rn(__fadd_rn(__fadd_rn(__fmul_rn(v.x, v.x),
                                                __fmul_rn(v.y, v.y)),
                                      __fmul_rn(v.z, v.z)),
                            __fmul_rn(v.w, v.w));
        #pragma unroll
        for (int off = 16; off >= 1; off >>= 1)
            p = __fadd_rn(p, __shfl_down_sync(0xffffffffu, p, off));
        if (lane == 0) rn2s[r] = p;
    }
    if (tid < BM) cand[tid] = ~0ull;

    // ---- A fragments -> registers (one-time; warp owns rows w*16..w*16+15) ----
    uint32_t aF[16][4];
    {
        const float* srow = src + (size_t)(m0blk + wid * 16) * DIM;
        #pragma unroll
        for (int ks = 0; ks < 16; ks++) {
            int k = ks * 8 + c_lane;
            aF[ks][0] = tf32_of(__ldg(srow + r_lane * DIM + k));
            aF[ks][1] = tf32_of(__ldg(srow + (r_lane + 8) * DIM + k));
            aF[ks][2] = tf32_of(__ldg(srow + r_lane * DIM + k + 4));
            aF[ks][3] = tf32_of(__ldg(srow + (r_lane + 8) * DIM + k + 4));
        }
    }

    // extra-K A fragment: A[m][0]=A[m][1]=1 (bias columns)
    uint32_t aHe[4];
    aHe[0] = aHe[1] = (c_lane <= 1) ? __float_as_uint(1.0f) : 0u;
    aHe[2] = aHe[3] = 0u;

    // ---- stage first B tile: 32 codes x 128 d, coalesced float4 ----
    {
        int c = wid, d4 = lane;   // warp w loads codes w, w+4, ...
        #pragma unroll
        for (int j = 0; j < 8; j++) {
            float4 v = __ldg(emb4 + (size_t)(c + 4 * j) * 32 + d4);
            *reinterpret_cast<uint4*>(&Bs[0][(c + 4 * j) * BROW + 4 * d4]) =
                *reinterpret_cast<uint4*>(&v);
        }
    }
    __syncthreads();

    // per-thread packed top-2 in s-domain, h = row-half (r_lane / r_lane+8)
    unsigned long long b1[2] = {~0ull, ~0ull}, b2[2] = {~0ull, ~0ull};

    for (int it = 0; it < NITER; it++) {
        const int buf = it & 1;
        const int n0 = it * 32;

        // prefetch next tile into registers (overlaps with mma below)
        float4 pre[8];
        if (it + 1 < NITER) {
            int c = wid, d4 = lane;
            #pragma unroll
            for (int j = 0; j < 8; j++)
                pre[j] = __ldg(emb4 + (size_t)(32 * (it + 1) + c + 4 * j) * 32 + d4);
        }

        float acc[4][4];
        #pragma unroll
        for (int nt = 0; nt < 4; nt++)
            #pragma unroll
            for (int q = 0; q < 4; q++) acc[nt][q] = 0.f;

        #pragma unroll
        for (int ks = 0; ks < 16; ks++) {
            #pragma unroll
            for (int nt = 0; nt < 4; nt++) {
                int a0 = (nt * 8 + r_lane) * BROW + ks * 8 + c_lane;
                uint32_t bh0 = Bs[buf][a0];        // raw fp32 bits, HW truncates
                uint32_t bh1 = Bs[buf][a0 + 4];
                MMA_TF32(acc[nt], aF[ks], bh0, bh1);
            }
        }

        // bias fold: k=0 -> -128 (exact), k=1 -> -en2/2
        #pragma unroll
        for (int nt = 0; nt < 4; nt++) {
            int code = n0 + nt * 8 + r_lane;
            uint32_t bh0 = 0u;
            if (c_lane == 0) bh0 = __float_as_uint(-128.0f);
            if (c_lane == 1)
                bh0 = __float_as_uint(__fmul_rn(-0.5f, __ldg(en2g + code)));
            MMA_TF32(acc[nt], aHe, bh0, 0u);
        }

        // slim epilogue: s = -2*acc > 0, packed top-2
        #pragma unroll
        for (int nt = 0; nt < 4; nt++) {
            int kk0 = n0 + nt * 8 + 2 * c_lane;
            #pragma unroll
            for (int q = 0; q < 4; q++) {
                int   h  = q >> 1;
                int   kk = kk0 + (q & 1);
                float s  = __fmul_rn(-2.0f, acc[nt][q]);
                unsigned long long p =
                    ((unsigned long long)__float_as_uint(s) << 32) | (unsigned)kk;
                unsigned long long hi = umax64(b1[h], p);
                b1[h] = umin64(b1[h], p);
                b2[h] = umin64(b2[h], hi);
            }
        }

        // commit prefetched tile and flip
        if (it + 1 < NITER) {
            int c = wid, d4 = lane;
            #pragma unroll
            for (int j = 0; j < 8; j++)
                *reinterpret_cast<uint4*>(
                    &Bs[1 - buf][(c + 4 * j) * BROW + 4 * d4]) =
                    *reinterpret_cast<uint4*>(&pre[j]);
        }
        __syncthreads();
    }

    // ---- per-row approx min via 4-lane butterfly, then exact rescoring ----
    #pragma unroll
    for (int h = 0; h < 2; h++) {
        unsigned long long v = b1[h];
        #pragma unroll
        for (int off = 1; off <= 2; off <<= 1)
            v = umin64(v, __shfl_xor_sync(0xffffffffu, v, off));
        float cut = __uint_as_float((uint32_t)(v >> 32)) + MARGIN;

        int row = wid * 16 + r_lane + 8 * h;
        const float4* srow4 = src4 + (size_t)row * (DIM / 4);
        float v1 = __uint_as_float((uint32_t)(b1[h] >> 32));
        float v2 = __uint_as_float((uint32_t)(b2[h] >> 32));
        if (v1 <= cut)
            rescore(srow4, embed, en2g, rn2s, cand, row,
                    (int)(unsigned)(b1[h] & 0xFFFFFFFFull));
        if (v2 <= cut)
            rescore(srow4, embed, en2g, rn2s, cand, row,
                    (int)(unsigned)(b2[h] & 0xFFFFFFFFull));
    }
    __syncthreads();

    if (tid < BM)
        idx_out[m0blk + tid] = (float)(unsigned)(cand[tid] & 0xFFFFFFFFull);
}

// ---------------------------------------------------------------------------
// residual: dst = src - gather(e[idx]), exact fsub. dst may alias src.
// ---------------------------------------------------------------------------
__global__ void __launch_bounds__(256)
residual_kernel(const float* __restrict__ src,
                const float* __restrict__ embed,
                const float* __restrict__ idx_lvl,
                float* __restrict__ dst,
                int early)
{
    if (early) return;
    int i = blockIdx.x * 256 + threadIdx.x;
    int row = i >> 5, c = i & 31;
    int k = __float2int_rn(idx_lvl[row]);
    float4 v = reinterpret_cast<const float4*>(src)[i];
    float4 e = reinterpret_cast<const float4*>(embed + (size_t)k * DIM)[c];
    v.x = __fsub_rn(v.x, e.x);
    v.y = __fsub_rn(v.y, e.y);
    v.z = __fsub_rn(v.z, e.z);
    v.w = __fsub_rn(v.w, e.w);
    reinterpret_cast<float4*>(dst)[i] = v;
}

__global__ void init3_kernel(float* __restrict__ out3, int early)
{
    if (early) return;
    if (threadIdx.x < 3) out3[threadIdx.x] = 0.f;
}

// ---------------------------------------------------------------------------
// final fused pass (unchanged from the validated R7 kernel)
// ---------------------------------------------------------------------------
__global__ void __launch_bounds__(256)
final_kernel(const float* __restrict__ inputs,
             const float* __restrict__ embedding,
             const float* __restrict__ idx_all,
             float* __restrict__ out_q,
             float* __restrict__ out3,
             int early)
{
    if (early) return;
    __shared__ float red[256];

    int tid = threadIdx.x;
    int d   = tid & 127;
    float acc = 0.f;

    #pragma unroll
    for (int it = 0; it < FINAL_ROWS / 2; it++) {
        int row = blockIdx.x * FINAL_ROWS + it * 2 + (tid >> 7);
        size_t o = (size_t)row * DIM + d;
        float inp = inputs[o];
        float r = inp, qs, e, diff;
        int k;

        k = __float2int_rn(idx_all[row]);
        e = embedding[((size_t)0 * NCODE + k) * DIM + d];
        diff = __fsub_rn(e, r); acc = fmaf(diff, diff, acc);
        qs = e; r = __fsub_rn(r, e);

        k = __float2int_rn(idx_all[(size_t)1 * NTOK + row]);
        e = embedding[((size_t)1 * NCODE + k) * DIM + d];
        diff = __fsub_rn(e, r); acc = fmaf(diff, diff, acc);
        qs = __fadd_rn(qs, e); r = __fsub_rn(r, e);

        k = __float2int_rn(idx_all[(size_t)2 * NTOK + row]);
        e = embedding[((size_t)2 * NCODE + k) * DIM + d];
        diff = __fsub_rn(e, r); acc = fmaf(diff, diff, acc);
        qs = __fadd_rn(qs, e); r = __fsub_rn(r, e);

        k = __float2int_rn(idx_all[(size_t)3 * NTOK + row]);
        e = embedding[((size_t)3 * NCODE + k) * DIM + d];
        diff = __fsub_rn(e, r); acc = fmaf(diff, diff, acc);
        qs = __fadd_rn(qs, e);

        out_q[o] = __fadd_rn(inp, __fsub_rn(qs, inp));
    }

    red[tid] = acc;
    __syncthreads();
    #pragma unroll
    for (int s = 128; s > 0; s >>= 1) {
        if (tid < s) red[tid] += red[tid + s];
        __syncthreads();
    }
    if (tid == 0) atomicAdd(&out3[1], red[0]);
}

__global__ void scalars_kernel(float* __restrict__ out3, int early)
{
    if (early) return;
    if (threadIdx.x == 0) {
        float cb = __fmul_rn(out3[1], 1.0f / 16777216.0f);
        out3[0] = __fadd_rn(cb, __fmul_rn(0.25f, cb));
        out3[1] = cb;
        out3[2] = cb;
    }
}

// ---------------------------------------------------------------------------
namespace {
struct ModuleEagerLoad {
    ModuleEagerLoad() {
        cudaFree(0);
        size_t f0 = 0, f1 = 0, tot = 0;
        cudaMemGetInfo(&f0, &tot);

        void* p;
        cudaGetSymbolAddress(&p, g_en2);

        prep_kernel<<<PREP_GRID, 256>>>(nullptr, 1);
        argmin_kernel<<<ARGMIN_GRID, 128>>>(nullptr, nullptr, nullptr, nullptr, 1);
        residual_kernel<<<RES_GRID, 256>>>(nullptr, nullptr, nullptr, nullptr, 1);
        init3_kernel<<<1, 32>>>(nullptr, 1);
        final_kernel<<<FINAL_GRID, 256>>>(nullptr, nullptr, nullptr, nullptr, nullptr, 1);
        scalars_kernel<<<1, 32>>>(nullptr, 1);
        cudaDeviceSynchronize();

        cudaMemGetInfo(&f1, &tot);
        fprintf(stderr, "[eager] free before=%zu after=%zu delta=%lld\n",
                f0, f1, (long long)f0 - (long long)f1);
    }
};
static ModuleEagerLoad s_eager_load;
}  // namespace

// ---------------------------------------------------------------------------
extern "C" void kernel_launch(void* const* d_in, const int* in_sizes, int n_in,
                              void* d_out, int out_size)
{
    const float* inputs    = (const float*)d_in[0];
    const float* embedding = (const float*)d_in[1];

    float* out     = (float*)d_out;
    float* out_q   = out;                            // N*D: residual scratch, then quantized_sum
    float* out_idx = out + (size_t)NTOK * DIM;       // L*N indices (as f32)
    float* out3    = out_idx + (size_t)NLVL * NTOK;  // vq, codebook, commit

    float* en2_base = nullptr;
    cudaGetSymbolAddress((void**)&en2_base, g_en2);

    init3_kernel<<<1, 32>>>(out3, 0);
    prep_kernel<<<PREP_GRID, 256>>>(embedding, 0);
    for (int lvl = 0; lvl < NLVL; lvl++) {
        const float* emb_l = embedding + (size_t)lvl * NCODE * DIM;
        const float* src   = (lvl == 0) ? inputs : out_q;
        argmin_kernel<<<ARGMIN_GRID, 128>>>(
            src, emb_l, en2_base + (size_t)lvl * NCODE,
            out_idx + (size_t)lvl * NTOK, 0);
        if (lvl < NLVL - 1)
            residual_kernel<<<RES_GRID, 256>>>(
                src, emb_l, out_idx + (size_t)lvl * NTOK, out_q, 0);
    }
    final_kernel<<<FINAL_GRID, 256>>>(inputs, embedding, out_idx, out_q, out3, 0);
    scalars_kernel<<<1, 32>>>(out3, 0);
}